// round 16
// baseline (speedup 1.0000x reference)
#include <cuda_runtime.h>
#include <cstdint>

// ---------------------------------------------------------------------------
// ClassificationNCA: 20-step NCA. Round 16:
//  - fire/nonfire lists precomputed ONCE for all steps, PER (step, batch)
//    (round-13 locality + round-14 launch hoisting).
//  - step kernel grid (21,16): per-batch MLP tiles (round-13 body verbatim)
//    + surplus tiles copy that batch's non-firing pixels (tile 20 is always
//    surplus -> coverage guaranteed).
// ---------------------------------------------------------------------------

#define kNCH 29
#define kBatch 16
#define kPix 4096
#define kStateElems (kBatch * kNCH * kPix)
#define kSteps 20
#define kGridX 21

// smem layout (floats) — identical to round 4/13
#define kH1Off 16384              /* region A: P[88][128] / H2[128][128] */
#define kWsOff (kH1Off + 32768)   /* H1 = 256*128 */
#define kWsFloats 8192
#define kSmemFloats (kWsOff + kWsFloats)
#define kSmemBytes (kSmemFloats * 4) /* 229376 B -> 1 CTA/SM */

__device__ float g_state[2][kStateElems];
__device__ int g_fcnt[kSteps][kBatch];
__device__ int g_nfcnt[kSteps][kBatch];
__device__ uint16_t g_plist[kSteps][kBatch][kPix];
__device__ uint16_t g_nplist[kSteps][kBatch][kPix];

// ---------------------------------------------------------------------------
// packed f32x2 helpers
// ---------------------------------------------------------------------------
__device__ __forceinline__ unsigned long long pack2(float x, float y)
{
    unsigned long long r;
    asm("mov.b64 %0, {%1, %2};" : "=l"(r) : "f"(x), "f"(y));
    return r;
}
__device__ __forceinline__ unsigned long long ffma2(unsigned long long a,
                                                    unsigned long long b,
                                                    unsigned long long c)
{
    unsigned long long d;
    asm("fma.rn.f32x2 %0, %1, %2, %3;" : "=l"(d) : "l"(a), "l"(b), "l"(c));
    return d;
}
__device__ __forceinline__ float2 unpack2(unsigned long long v)
{
    float2 f;
    asm("mov.b64 {%0, %1}, %2;" : "=f"(f.x), "=f"(f.y) : "l"(v));
    return f;
}

// ---------------------------------------------------------------------------
// threefry2x32, JAX key schedule (20 rounds)
// ---------------------------------------------------------------------------
#define TF_ROUND(r) { x0 += x1; x1 = (x1 << (r)) | (x1 >> (32 - (r))); x1 ^= x0; }
__host__ __device__ inline void threefry2x32(uint32_t k0, uint32_t k1,
                                             uint32_t x0, uint32_t x1,
                                             uint32_t &o0, uint32_t &o1)
{
    uint32_t k2 = k0 ^ k1 ^ 0x1BD11BDAu;
    x0 += k0; x1 += k1;
    TF_ROUND(13) TF_ROUND(15) TF_ROUND(26) TF_ROUND(6)
    x0 += k1; x1 += k2 + 1u;
    TF_ROUND(17) TF_ROUND(29) TF_ROUND(16) TF_ROUND(24)
    x0 += k2; x1 += k0 + 2u;
    TF_ROUND(13) TF_ROUND(15) TF_ROUND(26) TF_ROUND(6)
    x0 += k0; x1 += k1 + 3u;
    TF_ROUND(17) TF_ROUND(29) TF_ROUND(16) TF_ROUND(24)
    x0 += k1; x1 += k2 + 4u;
    TF_ROUND(13) TF_ROUND(15) TF_ROUND(26) TF_ROUND(6)
    x0 += k2; x1 += k0 + 5u;
    o0 = x0; o1 = x1;
}

// XLA ErfInv (f32), Giles polynomial — matches jax.lax.erf_inv
__device__ inline float erfinv_f(float x)
{
    float w = -log1pf(-x * x);
    float p;
    if (w < 5.0f) {
        w -= 2.5f;
        p = 2.81022636e-08f;
        p = fmaf(p, w, 3.43273939e-07f);
        p = fmaf(p, w, -3.5233877e-06f);
        p = fmaf(p, w, -4.39150654e-06f);
        p = fmaf(p, w, 0.00021858087f);
        p = fmaf(p, w, -0.00125372503f);
        p = fmaf(p, w, -0.00417768164f);
        p = fmaf(p, w, 0.246640727f);
        p = fmaf(p, w, 1.50140941f);
    } else {
        w = sqrtf(w) - 3.0f;
        p = -0.000200214257f;
        p = fmaf(p, w, 0.000100950558f);
        p = fmaf(p, w, 0.00134934322f);
        p = fmaf(p, w, -0.00367342844f);
        p = fmaf(p, w, 0.00573950773f);
        p = fmaf(p, w, -0.0076224613f);
        p = fmaf(p, w, 0.00943887047f);
        p = fmaf(p, w, 1.00167406f);
        p = fmaf(p, w, 2.83297682f);
    }
    return p * x;
}

// ---------------------------------------------------------------------------
// init: channels 0-2 = image (both buffers), 3-18 = threefry normal, 19-28 = 0
// also zeroes the per-(step,batch) list counters (graph-replay safe).
// ---------------------------------------------------------------------------
__global__ void __launch_bounds__(256) nca_init_kernel(const float* __restrict__ x,
                                                       uint32_t hk0, uint32_t hk1)
{
    int e = blockIdx.x * 256 + threadIdx.x;
    if (e >= kStateElems) return;
    if (e < kSteps * kBatch) { ((int*)g_fcnt)[e] = 0; ((int*)g_nfcnt)[e] = 0; }
    int b = e / (kNCH * kPix);
    int r = e - b * (kNCH * kPix);
    int c = r / kPix;
    int pix = r - c * kPix;

    if (c < 3) {
        float v = x[(b * 3 + c) * kPix + pix];
        g_state[0][e] = v;
        g_state[1][e] = v;
    } else if (c < 19) {
        const uint32_t HALF = 524288u;  // (16*16*4096)/2
        uint32_t i = (uint32_t)((b * 16 + (c - 3)) * kPix + pix);
        uint32_t lo = (i < HALF) ? i : (i - HALF);
        uint32_t o0, o1;
        threefry2x32(hk0, hk1, lo, lo + HALF, o0, o1);
        uint32_t bits = (i < HALF) ? o0 : o1;
        float f = __uint_as_float((bits >> 9) | 0x3f800000u) - 1.0f;
        const float LOV = -0.99999994f;               // nextafter(-1, 0)
        float u = fmaxf(LOV, f * 2.0f + LOV);         // (hi - lo) rounds to 2.0f
        float z = 1.41421356f * erfinv_f(u);
        g_state[0][e] = 0.5f + 0.225f * z;
    } else {
        g_state[0][e] = 0.0f;
    }
}

// ---------------------------------------------------------------------------
// list precompute: for every step, compact firing / non-firing pixel ids
// PER BATCH. grid (64, 20) x 1024. Fire bit depends only on (step, pixel).
// A warp spans 32 consecutive pixels of one batch (4096 % 32 == 0).
// ---------------------------------------------------------------------------
__global__ void __launch_bounds__(1024) nca_lists_kernel()
{
    const int step = blockIdx.y;
    const int e = blockIdx.x * 1024 + threadIdx.x;   // 0..65535
    const int b = e >> 12;
    const int pix = e & 4095;

    // fold_in(key(42), step)
    uint32_t fk0, fk1;
    threefry2x32(0u, 42u, 0u, (uint32_t)step, fk0, fk1);

    // fire: uniform < 0.5  <=>  top bit of bits == 0
    const uint32_t HALF = 32768u;
    uint32_t n = (uint32_t)e;
    uint32_t lo = (n < HALF) ? n : (n - HALF);
    uint32_t o0, o1;
    threefry2x32(fk0, fk1, lo, lo + HALF, o0, o1);
    uint32_t bits = (n < HALF) ? o0 : o1;
    bool fire = (bits & 0x80000000u) == 0u;

    unsigned m = __ballot_sync(0xffffffffu, fire);
    int lane = threadIdx.x & 31;
    int fb = 0, nb = 0;
    if (lane == 0) {
        fb = atomicAdd(&g_fcnt[step][b], __popc(m));
        nb = atomicAdd(&g_nfcnt[step][b], 32 - __popc(m));
    }
    fb = __shfl_sync(0xffffffffu, fb, 0);
    nb = __shfl_sync(0xffffffffu, nb, 0);

    if (fire)
        g_plist[step][b][fb + __popc(m & ((1u << lane) - 1u))] = (uint16_t)pix;
    else
        g_nplist[step][b][nb + __popc(~m & ((1u << lane) - 1u))] = (uint16_t)pix;
}

// ---------------------------------------------------------------------------
// fused step kernel: grid (21, 16) x 512 threads.
//   blockIdx.x <  tiles_b : MLP on 128 compacted firing slots (round-13 body)
//   blockIdx.x >= tiles_b : copy-through worker for batch b's non-firing px
// tile 20 is always surplus (empirically tiles_b <= 20), so coverage holds.
// ---------------------------------------------------------------------------
__global__ void __launch_bounds__(512, 1) nca_step_kernel(
    const float* __restrict__ w1, const float* __restrict__ b1,
    const float* __restrict__ w2, const float* __restrict__ w3,
    float tval, int step, int srcbuf)
{
    extern __shared__ float smem[];
    float* P   = smem;           // [88][128]
    float* H1s = smem + kH1Off;  // [256][128]
    float* H2s = smem;           // [128][128] (reuses P region)
    float* Ws  = smem + kWsOff;  // weight staging, 8192 floats

    const float* __restrict__ src = g_state[srcbuf];
    float* __restrict__ dst = g_state[srcbuf ^ 1];

    const int b = blockIdx.y;
    const int nf = g_fcnt[step][b];
    const int tiles = (nf + 127) >> 7;
    const int tid = threadIdx.x;

    if ((int)blockIdx.x >= tiles) {
        // ---- copy worker: this batch's non-firing pixels, ch 3..28 ----
        const int W = kGridX - tiles;
        const int wi = blockIdx.x - tiles;
        const int nn = g_nfcnt[step][b];
        const int bb = b * (kNCH * kPix) + 3 * kPix;
        for (int j = wi * 512 + tid; j < nn; j += W * 512) {
            int px = (int)g_nplist[step][b][j];
#pragma unroll
            for (int c = 0; c < 26; ++c)
                dst[bb + c * kPix + px] = __ldg(&src[bb + c * kPix + px]);
        }
        return;
    }

    const int pix  = tid & 127;          // slot-local index
    const int grp4 = tid >> 7;           // 0..3
    const int slot = blockIdx.x * 128 + pix;
    const bool real = slot < nf;
    const int px = (int)g_plist[step][b][slot];   // stale-but-valid if !real
    const int gx = px & 63;
    const int gy = px >> 6;

    // ---- phase 1: perception (s, sobel_x, sobel_y, t) -> P ----
    {
        const float* sb = src + b * (kNCH * kPix);
        const int cbeg = grp4 * 8;
        const int cend = (cbeg + 8 < 29) ? cbeg + 8 : 29;
        const bool ym = gy > 0, yp = gy < 63, xm = gx > 0, xp = gx < 63;
        for (int c = cbeg; c < cend; ++c) {
            const float* sc = sb + c * kPix;
            float v11 = __ldg(&sc[gy * 64 + gx]);
            float v01 = ym ? __ldg(&sc[(gy - 1) * 64 + gx]) : 0.f;
            float v21 = yp ? __ldg(&sc[(gy + 1) * 64 + gx]) : 0.f;
            float v10 = xm ? __ldg(&sc[gy * 64 + gx - 1]) : 0.f;
            float v12 = xp ? __ldg(&sc[gy * 64 + gx + 1]) : 0.f;
            float v00 = (ym && xm) ? __ldg(&sc[(gy - 1) * 64 + gx - 1]) : 0.f;
            float v02 = (ym && xp) ? __ldg(&sc[(gy - 1) * 64 + gx + 1]) : 0.f;
            float v20 = (yp && xm) ? __ldg(&sc[(gy + 1) * 64 + gx - 1]) : 0.f;
            float v22 = (yp && xp) ? __ldg(&sc[(gy + 1) * 64 + gx + 1]) : 0.f;
            float sx = ((v02 - v00) + 2.0f * (v12 - v10) + (v22 - v20)) * 0.125f;
            float sy = ((v20 - v00) + 2.0f * (v21 - v01) + (v22 - v02)) * 0.125f;
            P[c * 128 + pix] = v11;
            P[(29 + c) * 128 + pix] = sx;
            P[(58 + c) * 128 + pix] = sy;
        }
        if (grp4 == 0) P[87 * 128 + pix] = tval;
    }

    const int og = tid >> 5;   // warp id 0..15 (uniform -> broadcast LDS)
    const int pb = (tid & 31) << 2;  // slot base, 4 slots / thread

    // ---- layer 1: h1 = leaky(W1 @ p + b1), 256 outs, k = 88 ----
    for (int chunk = 0; chunk < 2; ++chunk) {
        const int obase = og * 16 + chunk * 8;
        unsigned long long acc[4][4];
#pragma unroll
        for (int p = 0; p < 4; ++p) {
            unsigned long long bp = pack2(__ldg(&b1[obase + 2 * p]),
                                          __ldg(&b1[obase + 2 * p + 1]));
            acc[p][0] = bp; acc[p][1] = bp; acc[p][2] = bp; acc[p][3] = bp;
        }
        for (int ks = 0; ks < 88; ks += 44) {
            __syncthreads();
            // stage transposed: Ws[kk*128 + ol], ol -> weight row for this chunk
            for (int i = tid; i < 44 * 128; i += 512) {
                int kk = i >> 7;
                int ol = i & 127;
                int row = (ol >> 3) * 16 + chunk * 8 + (ol & 7);
                Ws[i] = __ldg(&w1[row * 88 + ks + kk]);
            }
            __syncthreads();
#pragma unroll 2
            for (int kk = 0; kk < 44; ++kk) {
                float4 pv = *reinterpret_cast<const float4*>(&P[(ks + kk) * 128 + pb]);
                const ulonglong2 wA = *reinterpret_cast<const ulonglong2*>(&Ws[kk * 128 + og * 8]);
                const ulonglong2 wB = *reinterpret_cast<const ulonglong2*>(&Ws[kk * 128 + og * 8 + 4]);
                unsigned long long px4[4];
                px4[0] = pack2(pv.x, pv.x); px4[1] = pack2(pv.y, pv.y);
                px4[2] = pack2(pv.z, pv.z); px4[3] = pack2(pv.w, pv.w);
#pragma unroll
                for (int j = 0; j < 4; ++j) {
                    acc[0][j] = ffma2(wA.x, px4[j], acc[0][j]);
                    acc[1][j] = ffma2(wA.y, px4[j], acc[1][j]);
                    acc[2][j] = ffma2(wB.x, px4[j], acc[2][j]);
                    acc[3][j] = ffma2(wB.y, px4[j], acc[3][j]);
                }
            }
        }
#pragma unroll
        for (int p = 0; p < 4; ++p) {
            float lo4[4], hi4[4];
#pragma unroll
            for (int j = 0; j < 4; ++j) {
                float2 f = unpack2(acc[p][j]);
                lo4[j] = f.x >= 0.f ? f.x : 0.01f * f.x;
                hi4[j] = f.y >= 0.f ? f.y : 0.01f * f.y;
            }
            *reinterpret_cast<float4*>(&H1s[(obase + 2 * p) * 128 + pb]) =
                make_float4(lo4[0], lo4[1], lo4[2], lo4[3]);
            *reinterpret_cast<float4*>(&H1s[(obase + 2 * p + 1) * 128 + pb]) =
                make_float4(hi4[0], hi4[1], hi4[2], hi4[3]);
        }
    }

    // ---- layer 2: h2 = leaky(W2 @ h1), 128 outs, k = 256 ----
    {
        const int obase = og * 8;
        unsigned long long acc[4][4];
#pragma unroll
        for (int p = 0; p < 4; ++p) {
            acc[p][0] = 0ull; acc[p][1] = 0ull; acc[p][2] = 0ull; acc[p][3] = 0ull;
        }
        for (int ks = 0; ks < 256; ks += 64) {
            __syncthreads();
            for (int i = tid; i < 64 * 128; i += 512) {
                int kk = i >> 7;
                int ol = i & 127;
                Ws[i] = __ldg(&w2[ol * 256 + ks + kk]);
            }
            __syncthreads();
#pragma unroll 2
            for (int kk = 0; kk < 64; ++kk) {
                float4 hv = *reinterpret_cast<const float4*>(&H1s[(ks + kk) * 128 + pb]);
                const ulonglong2 wA = *reinterpret_cast<const ulonglong2*>(&Ws[kk * 128 + og * 8]);
                const ulonglong2 wB = *reinterpret_cast<const ulonglong2*>(&Ws[kk * 128 + og * 8 + 4]);
                unsigned long long px4[4];
                px4[0] = pack2(hv.x, hv.x); px4[1] = pack2(hv.y, hv.y);
                px4[2] = pack2(hv.z, hv.z); px4[3] = pack2(hv.w, hv.w);
#pragma unroll
                for (int j = 0; j < 4; ++j) {
                    acc[0][j] = ffma2(wA.x, px4[j], acc[0][j]);
                    acc[1][j] = ffma2(wA.y, px4[j], acc[1][j]);
                    acc[2][j] = ffma2(wB.x, px4[j], acc[2][j]);
                    acc[3][j] = ffma2(wB.y, px4[j], acc[3][j]);
                }
            }
        }
#pragma unroll
        for (int p = 0; p < 4; ++p) {
            float lo4[4], hi4[4];
#pragma unroll
            for (int j = 0; j < 4; ++j) {
                float2 f = unpack2(acc[p][j]);
                lo4[j] = f.x >= 0.f ? f.x : 0.01f * f.x;
                hi4[j] = f.y >= 0.f ? f.y : 0.01f * f.y;
            }
            *reinterpret_cast<float4*>(&H2s[(obase + 2 * p) * 128 + pb]) =
                make_float4(lo4[0], lo4[1], lo4[2], lo4[3]);
            *reinterpret_cast<float4*>(&H2s[(obase + 2 * p + 1) * 128 + pb]) =
                make_float4(hi4[0], hi4[1], hi4[2], hi4[3]);
        }
    }

    // ---- layer 3 (channels 3..28) + unconditional update of firing px ----
    __syncthreads();
    for (int i = tid; i < 29 * 128; i += 512) Ws[i] = __ldg(&w3[i]);
    __syncthreads();
    {
        // grp4 0..3 handle {7,7,6,6} channels starting at {3,10,17,23}
        const int obase = (grp4 < 2) ? (3 + grp4 * 7) : (17 + (grp4 - 2) * 6);
        const int cnt   = (grp4 < 2) ? 7 : 6;
        float dxv[7];
#pragma unroll
        for (int u = 0; u < 7; ++u) dxv[u] = 0.f;
#pragma unroll 2
        for (int k = 0; k < 128; ++k) {
            float h = H2s[k * 128 + pix];
#pragma unroll
            for (int u = 0; u < 7; ++u)
                dxv[u] = fmaf(Ws[(obase + u) * 128 + k], h, dxv[u]);
        }
        if (real) {
            int base = b * (kNCH * kPix) + px;
#pragma unroll
            for (int u = 0; u < 7; ++u) {
                if (u < cnt) {
                    int idx = base + (obase + u) * kPix;
                    dst[idx] = __ldg(&src[idx]) + dxv[u];
                }
            }
        }
    }
}

// ---------------------------------------------------------------------------
// reduce: mean over HW of channels 19..28, then softmax -> out (16, 10)
// ---------------------------------------------------------------------------
__global__ void __launch_bounds__(256) nca_reduce_kernel(float* __restrict__ out)
{
    int b = blockIdx.x;
    int tid = threadIdx.x;
    const float* st = g_state[0] + (b * kNCH + 19) * kPix;
    float acc[10];
#pragma unroll
    for (int c = 0; c < 10; ++c) acc[c] = 0.f;
    for (int i = tid; i < kPix; i += 256) {
#pragma unroll
        for (int c = 0; c < 10; ++c) acc[c] += st[c * kPix + i];
    }
#pragma unroll
    for (int c = 0; c < 10; ++c) {
#pragma unroll
        for (int off = 16; off > 0; off >>= 1)
            acc[c] += __shfl_xor_sync(0xffffffffu, acc[c], off);
    }
    __shared__ float sred[10][8];
    int wid = tid >> 5, lane = tid & 31;
    if (lane == 0) {
#pragma unroll
        for (int c = 0; c < 10; ++c) sred[c][wid] = acc[c];
    }
    __syncthreads();
    if (tid == 0) {
        float m[10];
        float mx = -1e30f;
#pragma unroll
        for (int c = 0; c < 10; ++c) {
            float s = 0.f;
#pragma unroll
            for (int w = 0; w < 8; ++w) s += sred[c][w];
            m[c] = s * (1.0f / 4096.0f);
            mx = fmaxf(mx, m[c]);
        }
        float den = 0.f;
        float e[10];
#pragma unroll
        for (int c = 0; c < 10; ++c) { e[c] = expf(m[c] - mx); den += e[c]; }
#pragma unroll
        for (int c = 0; c < 10; ++c) out[b * 10 + c] = e[c] / den;
    }
}

// ---------------------------------------------------------------------------
extern "C" void kernel_launch(void* const* d_in, const int* in_sizes, int n_in,
                              void* d_out, int out_size)
{
    (void)in_sizes; (void)n_in; (void)out_size;
    const float* x  = (const float*)d_in[0];
    const float* w1 = (const float*)d_in[1];
    const float* b1 = (const float*)d_in[2];
    const float* w2 = (const float*)d_in[3];
    const float* w3 = (const float*)d_in[4];
    float* out = (float*)d_out;

    cudaFuncSetAttribute(nca_step_kernel,
                         cudaFuncAttributeMaxDynamicSharedMemorySize, kSmemBytes);

    // hid-init key: fold_in(key(42), 10000)
    uint32_t hk0, hk1;
    threefry2x32(0u, 42u, 0u, 10000u, hk0, hk1);
    nca_init_kernel<<<(kStateElems + 255) / 256, 256>>>(x, hk0, hk1);

    // precompute all 20 steps' per-batch fire/nonfire lists (state-independent)
    nca_lists_kernel<<<dim3(64, kSteps), 1024>>>();

    for (int s = 0; s < kSteps; ++s) {
        nca_step_kernel<<<dim3(kGridX, kBatch), 512, kSmemBytes>>>(
            w1, b1, w2, w3, (float)s / 100.0f, s, s & 1);
    }
    nca_reduce_kernel<<<16, 256>>>(out);
}